// round 8
// baseline (speedup 1.0000x reference)
#include <cuda_runtime.h>
#include <stdint.h>

#define NBINS    4096
#define CAND_CAP 2048
#define MAXN     524288
#define KSEL     64
#define TPB      256
#define SGRID    592    // 4 CTAs/SM x 148 SMs — proven-fastest for k_score

// Scratch (__device__ globals; zero at module load). Per-replay reset:
// g_count by k_score block0 at start (only touched later by k_compact —
// stream order makes this safe); g_hist by k_select blocks 64-79.
__device__ uint32_t            g_keys[MAXN];
__device__ uint32_t            g_hist[NBINS];
__device__ int                 g_count;
__device__ unsigned long long  g_cand[CAND_CAP];

__device__ __forceinline__ uint32_t f2key(float f) {
    uint32_t u = __float_as_uint(f);
    return (u & 0x80000000u) ? ~u : (u | 0x80000000u);
}
__device__ __forceinline__ float dot4(float4 a, float4 b) {
    return a.x*b.x + a.y*b.y + a.z*b.z + a.w*b.w;
}

// K1: EXACT R3 score loop (measured 83.2us @ 6.23TB/s): 4 rows per warp
// iteration -> 8 independent LDG.128 in flight, plain xor-shuffle
// reductions, fused smem histogram. NO epilogue, NO fence, NO ticket —
// those cost 6.5us of drain serialization in R7.
__global__ void k_score(const float4* __restrict__ q,
                        const float4* __restrict__ mat, int N) {
    __shared__ uint32_t sh[NBINS];
    if (blockIdx.x == 0 && threadIdx.x == 0) g_count = 0;   // replay reset
    for (int i = threadIdx.x; i < NBINS; i += TPB) sh[i] = 0u;
    __syncthreads();

    const int lane   = threadIdx.x & 31;
    const int warp   = (blockIdx.x * TPB + threadIdx.x) >> 5;
    const int nwarps = (SGRID * TPB) >> 5;

    const float4 qa = q[lane];
    const float4 qb = q[lane + 32];

    for (int r0 = warp * 4; r0 < N; r0 += nwarps * 4) {
        const float4* p = mat + (size_t)r0 * 64;
        if (r0 + 3 < N) {
            float4 a0 = p[lane],       b0 = p[lane + 32];
            float4 a1 = p[lane + 64],  b1 = p[lane + 96];
            float4 a2 = p[lane + 128], b2 = p[lane + 160];
            float4 a3 = p[lane + 192], b3 = p[lane + 224];
            float s0 = dot4(a0, qa) + dot4(b0, qb);
            float s1 = dot4(a1, qa) + dot4(b1, qb);
            float s2 = dot4(a2, qa) + dot4(b2, qb);
            float s3 = dot4(a3, qa) + dot4(b3, qb);
            #pragma unroll
            for (int o = 16; o; o >>= 1) {
                s0 += __shfl_xor_sync(0xffffffffu, s0, o);
                s1 += __shfl_xor_sync(0xffffffffu, s1, o);
                s2 += __shfl_xor_sync(0xffffffffu, s2, o);
                s3 += __shfl_xor_sync(0xffffffffu, s3, o);
            }
            if (lane < 4) {
                float s = (lane == 0) ? s0 : (lane == 1) ? s1 : (lane == 2) ? s2 : s3;
                uint32_t key = f2key(s);
                g_keys[r0 + lane] = key;
                atomicAdd(&sh[key >> 20], 1u);
            }
        } else {
            for (int r = r0; r < N; r++) {
                const float4* row = mat + (size_t)r * 64;
                float s = dot4(row[lane], qa) + dot4(row[lane + 32], qb);
                #pragma unroll
                for (int o = 16; o; o >>= 1) s += __shfl_xor_sync(0xffffffffu, s, o);
                if (lane == 0) {
                    uint32_t key = f2key(s);
                    g_keys[r] = key;
                    atomicAdd(&sh[key >> 20], 1u);
                }
            }
        }
    }
    __syncthreads();
    for (int i = threadIdx.x; i < NBINS; i += TPB) {
        uint32_t c = sh[i];
        if (c) atomicAdd(&g_hist[i], c);
    }
}

// K2: each block computes threshold bin B with a PARALLEL scan
// (256 threads x 16 __ldcg = one L2 round-trip, then short serial pass on
// smem partials), then compacts exactly one uint4 per thread.
// Packed key = (key32<<32) | ~idx : higher score first; ties -> smaller idx.
__global__ void k_compact(int N4) {
    __shared__ uint32_t part[TPB];
    __shared__ int sB;
    const int tid = threadIdx.x;

    // Parallel partial sums: thread t covers bins [t*16, t*16+16).
    uint32_t s = 0;
    #pragma unroll 16
    for (int j = 0; j < 16; j++)
        s += __ldcg(&g_hist[tid * 16 + j]);
    part[tid] = s;
    __syncthreads();
    if (tid == 0) {
        long long cum = 0;
        int seg = 0;
        for (int i = TPB - 1; i >= 0; i--) {
            cum += part[i];
            if (cum >= KSEL) { seg = i; break; }
        }
        long long c2 = cum - part[seg];
        int B = seg * 16;
        for (int b = seg * 16 + 15; b >= seg * 16; b--) {
            c2 += __ldcg(&g_hist[b]);
            if (c2 >= KSEL) { B = b; break; }
        }
        sB = B;
    }
    __syncthreads();
    const int B = sB;

    int i = blockIdx.x * TPB + tid;
    if (i >= N4) return;
    uint4 k4 = ((const uint4*)g_keys)[i];
    uint32_t base = (uint32_t)i * 4u;
    #pragma unroll
    for (int j = 0; j < 4; j++) {
        uint32_t key = (j == 0) ? k4.x : (j == 1) ? k4.y : (j == 2) ? k4.z : k4.w;
        if ((int)(key >> 20) >= B) {
            int p = atomicAdd(&g_count, 1);
            if (p < CAND_CAP)
                g_cand[p] = ((unsigned long long)key << 32)
                          | (uint32_t)(~(base + (uint32_t)j));
        }
    }
}

// K3: blocks 0-63: redundant rank computation (packed keys unique -> unique
// ranks; rank<64 selects) + gather ONE output row each. Block 0 also writes
// the index vector. Blocks 64-79: zero g_hist for the next replay.
__global__ void k_select(const float4* __restrict__ mat,
                         float* __restrict__ out, int out_size) {
    if (blockIdx.x >= KSEL) {
        int idx = (blockIdx.x - KSEL) * TPB + threadIdx.x;
        g_hist[idx] = 0u;
        return;
    }

    __shared__ unsigned long long cv[CAND_CAP];
    __shared__ uint32_t rows[KSEL];
    const int tid = threadIdx.x;

    int C = g_count;
    if (C > CAND_CAP) C = CAND_CAP;

    for (int j = tid; j < C; j += TPB) cv[j] = g_cand[j];
    __syncthreads();
    for (int j = tid; j < C; j += TPB) {
        unsigned long long v = cv[j];
        int rank = 0;
        for (int i = 0; i < C; i++) rank += (cv[i] > v);
        if (rank < KSEL) rows[rank] = ~(uint32_t)(v & 0xFFFFFFFFull);
    }
    __syncthreads();

    const int r = blockIdx.x;
    float4* out4 = (float4*)out;
    if (tid < 64)
        out4[r * 64 + tid] = mat[(size_t)rows[r] * 64 + tid];
    if (r == 0 && tid < KSEL && out_size >= KSEL * 256 + KSEL)
        out[KSEL * 256 + tid] = (float)rows[tid];
}

extern "C" void kernel_launch(void* const* d_in, const int* in_sizes, int n_in,
                              void* d_out, int out_size) {
    const float* q   = (const float*)d_in[0];   // [256]
    const float* mat = (const float*)d_in[1];   // [500000, 256]
    int D = in_sizes[0];
    int N = in_sizes[1] / D;
    int N4 = N / 4;

    k_score<<<SGRID, TPB>>>((const float4*)q, (const float4*)mat, N);
    k_compact<<<(N4 + TPB - 1) / TPB, TPB>>>(N4);
    k_select<<<KSEL + NBINS / TPB, TPB>>>((const float4*)mat, (float*)d_out, out_size);
}

// round 9
// speedup vs baseline: 1.0524x; 1.0524x over previous
#include <cuda_runtime.h>
#include <stdint.h>

#define NBINS    4096
#define CAND_CAP 2048
#define MAXN     524288
#define KSEL     64
#define TPB      256
#define SGRID    592    // 4 CTAs/SM x 148 SMs — proven-fastest for k_score

// Scratch (__device__ globals; zero at module load). Per-replay reset:
// g_count by k_score block0 at start (only touched later by k_compact —
// stream order makes this safe); g_hist by k_select blocks 64-79.
__device__ uint32_t            g_keys[MAXN];
__device__ uint32_t            g_hist[NBINS];
__device__ int                 g_count;
__device__ unsigned long long  g_cand[CAND_CAP];

__device__ __forceinline__ uint32_t f2key(float f) {
    uint32_t u = __float_as_uint(f);
    return (u & 0x80000000u) ? ~u : (u | 0x80000000u);
}
__device__ __forceinline__ float dot4(float4 a, float4 b) {
    return a.x*b.x + a.y*b.y + a.z*b.z + a.w*b.w;
}

// K1: EXACT R3/R8 score loop (measured 83-84us @ ~6.2TB/s). Do not touch.
__global__ void k_score(const float4* __restrict__ q,
                        const float4* __restrict__ mat, int N) {
    __shared__ uint32_t sh[NBINS];
    if (blockIdx.x == 0 && threadIdx.x == 0) g_count = 0;   // replay reset
    for (int i = threadIdx.x; i < NBINS; i += TPB) sh[i] = 0u;
    __syncthreads();

    const int lane   = threadIdx.x & 31;
    const int warp   = (blockIdx.x * TPB + threadIdx.x) >> 5;
    const int nwarps = (SGRID * TPB) >> 5;

    const float4 qa = q[lane];
    const float4 qb = q[lane + 32];

    for (int r0 = warp * 4; r0 < N; r0 += nwarps * 4) {
        const float4* p = mat + (size_t)r0 * 64;
        if (r0 + 3 < N) {
            float4 a0 = p[lane],       b0 = p[lane + 32];
            float4 a1 = p[lane + 64],  b1 = p[lane + 96];
            float4 a2 = p[lane + 128], b2 = p[lane + 160];
            float4 a3 = p[lane + 192], b3 = p[lane + 224];
            float s0 = dot4(a0, qa) + dot4(b0, qb);
            float s1 = dot4(a1, qa) + dot4(b1, qb);
            float s2 = dot4(a2, qa) + dot4(b2, qb);
            float s3 = dot4(a3, qa) + dot4(b3, qb);
            #pragma unroll
            for (int o = 16; o; o >>= 1) {
                s0 += __shfl_xor_sync(0xffffffffu, s0, o);
                s1 += __shfl_xor_sync(0xffffffffu, s1, o);
                s2 += __shfl_xor_sync(0xffffffffu, s2, o);
                s3 += __shfl_xor_sync(0xffffffffu, s3, o);
            }
            if (lane < 4) {
                float s = (lane == 0) ? s0 : (lane == 1) ? s1 : (lane == 2) ? s2 : s3;
                uint32_t key = f2key(s);
                g_keys[r0 + lane] = key;
                atomicAdd(&sh[key >> 20], 1u);
            }
        } else {
            for (int r = r0; r < N; r++) {
                const float4* row = mat + (size_t)r * 64;
                float s = dot4(row[lane], qa) + dot4(row[lane + 32], qb);
                #pragma unroll
                for (int o = 16; o; o >>= 1) s += __shfl_xor_sync(0xffffffffu, s, o);
                if (lane == 0) {
                    uint32_t key = f2key(s);
                    g_keys[r] = key;
                    atomicAdd(&sh[key >> 20], 1u);
                }
            }
        }
    }
    __syncthreads();
    for (int i = threadIdx.x; i < NBINS; i += TPB) {
        uint32_t c = sh[i];
        if (c) atomicAdd(&g_hist[i], c);
    }
}

// K2: fully-parallel threshold computation (no serial dependent chains),
// then compact exactly one uint4 per thread.
// Packed key = (key32<<32) | ~idx : higher score first; ties -> smaller idx.
__global__ void k_compact(int N4) {
    __shared__ uint32_t part[TPB];   // becomes suffix sums of coarse bins
    __shared__ int sB;
    const int tid = threadIdx.x;

    // Coarse partial: thread t covers fine bins [t*16, t*16+16). 16 parallel
    // __ldcg loads (MLP 16) — one pipelined L2 round trip.
    uint32_t v = 0;
    #pragma unroll 16
    for (int j = 0; j < 16; j++)
        v += __ldcg(&g_hist[tid * 16 + j]);
    part[tid] = v;
    __syncthreads();

    // Hillis-Steele suffix scan: part[t] = #keys in coarse bins >= t.
    #pragma unroll
    for (int off = 1; off < TPB; off <<= 1) {
        uint32_t add = (tid + off < TPB) ? part[tid + off] : 0u;
        __syncthreads();
        v += add;
        part[tid] = v;
        __syncthreads();
    }

    // Coarse seg: unique t with part[t] >= K and part[t+1] < K (suffix
    // non-increasing). Each thread tests its own slot — no loop.
    uint32_t nextC = (tid + 1 < TPB) ? part[tid + 1] : 0u;
    __shared__ int sSeg;
    if (part[tid] >= KSEL && nextC < KSEL) sSeg = tid;
    __syncthreads();
    const int seg = sSeg;
    const uint32_t above = (seg + 1 < TPB) ? part[seg + 1] : 0u;

    // Fine: warp 0 suffix-scans the 16 bins of seg via shuffles.
    if (tid < 32) {
        uint32_t h = (tid < 16) ? __ldcg(&g_hist[seg * 16 + tid]) : 0u;
        uint32_t fv = h;
        #pragma unroll
        for (int off = 1; off < 16; off <<= 1) {
            uint32_t o = __shfl_down_sync(0xffffffffu, fv, off);
            if (tid + off < 16) fv += o;
        }
        uint32_t nxt = __shfl_down_sync(0xffffffffu, fv, 1);  // lane15 reads lane16's 0
        if (tid < 16) {
            uint32_t cnt     = above + fv;
            uint32_t cntNext = above + ((tid == 15) ? 0u : nxt);
            if (cnt >= KSEL && cntNext < KSEL) sB = seg * 16 + tid;
        }
    }
    __syncthreads();
    const int B = sB;

    int i = blockIdx.x * TPB + tid;
    if (i >= N4) return;
    uint4 k4 = ((const uint4*)g_keys)[i];
    uint32_t base = (uint32_t)i * 4u;
    #pragma unroll
    for (int j = 0; j < 4; j++) {
        uint32_t key = (j == 0) ? k4.x : (j == 1) ? k4.y : (j == 2) ? k4.z : k4.w;
        if ((int)(key >> 20) >= B) {
            int p = atomicAdd(&g_count, 1);
            if (p < CAND_CAP)
                g_cand[p] = ((unsigned long long)key << 32)
                          | (uint32_t)(~(base + (uint32_t)j));
        }
    }
}

// K3: blocks 0-63: redundant rank computation (packed keys unique -> unique
// ranks; rank<64 selects) + gather ONE output row each. Block 0 also writes
// the index vector. Blocks 64-79: zero g_hist for the next replay.
__global__ void k_select(const float4* __restrict__ mat,
                         float* __restrict__ out, int out_size) {
    if (blockIdx.x >= KSEL) {
        int idx = (blockIdx.x - KSEL) * TPB + threadIdx.x;
        g_hist[idx] = 0u;
        return;
    }

    __shared__ unsigned long long cv[CAND_CAP];
    __shared__ uint32_t rows[KSEL];
    const int tid = threadIdx.x;

    int C = g_count;
    if (C > CAND_CAP) C = CAND_CAP;

    for (int j = tid; j < C; j += TPB) cv[j] = g_cand[j];
    __syncthreads();
    for (int j = tid; j < C; j += TPB) {
        unsigned long long v = cv[j];
        int rank = 0;
        for (int i = 0; i < C; i++) rank += (cv[i] > v);
        if (rank < KSEL) rows[rank] = ~(uint32_t)(v & 0xFFFFFFFFull);
    }
    __syncthreads();

    const int r = blockIdx.x;
    float4* out4 = (float4*)out;
    if (tid < 64)
        out4[r * 64 + tid] = mat[(size_t)rows[r] * 64 + tid];
    if (r == 0 && tid < KSEL && out_size >= KSEL * 256 + KSEL)
        out[KSEL * 256 + tid] = (float)rows[tid];
}

extern "C" void kernel_launch(void* const* d_in, const int* in_sizes, int n_in,
                              void* d_out, int out_size) {
    const float* q   = (const float*)d_in[0];   // [256]
    const float* mat = (const float*)d_in[1];   // [500000, 256]
    int D = in_sizes[0];
    int N = in_sizes[1] / D;
    int N4 = N / 4;

    k_score<<<SGRID, TPB>>>((const float4*)q, (const float4*)mat, N);
    k_compact<<<(N4 + TPB - 1) / TPB, TPB>>>(N4);
    k_select<<<KSEL + NBINS / TPB, TPB>>>((const float4*)mat, (float*)d_out, out_size);
}